// round 13
// baseline (speedup 1.0000x reference)
#include <cuda_runtime.h>
#include <cuda_bf16.h>
#include <cstdint>
#include <cstddef>

// ---------------------------------------------------------------------------
// Problem constants
// ---------------------------------------------------------------------------
#define BATCH   8
#define SEQ     2048
#define DIM     1024
#define HEADS   16
#define HDIM    64
#define TOKENS  (BATCH * SEQ)          // 16384
#define ELEMS   (TOKENS * DIM)         // 16,777,216

// ---------------------------------------------------------------------------
// Scratch (allocation-free rule: __device__ globals)
// ---------------------------------------------------------------------------
__device__ __align__(256) float g_Q[ELEMS];
__device__ __align__(256) float g_K[ELEMS];
__device__ __align__(256) float g_V[ELEMS];
__device__ __align__(256) float g_Y[ELEMS];             // attn out (fp32)
__device__ __align__(256) float g_Wt[4][DIM * DIM];     // weights, tf32 + interleaved

// ---------------------------------------------------------------------------
// PTX helpers (sm_80-level; tcgen05 rejected by compute_103 virtual arch)
// ---------------------------------------------------------------------------
__device__ __forceinline__ uint32_t smem_u32(const void* p) {
    uint32_t a;
    asm("{ .reg .u64 t; cvta.to.shared.u64 t, %1; cvt.u32.u64 %0, t; }"
        : "=r"(a) : "l"(p));
    return a;
}

__device__ __forceinline__ void cp_async16(uint32_t dst, const void* src) {
    asm volatile("cp.async.cg.shared.global [%0], [%1], 16;"
                 :: "r"(dst), "l"(src) : "memory");
}
__device__ __forceinline__ void cp_commit() {
    asm volatile("cp.async.commit_group;" ::: "memory");
}
template <int N>
__device__ __forceinline__ void cp_wait() {
    asm volatile("cp.async.wait_group %0;" :: "n"(N) : "memory");
}

__device__ __forceinline__ uint32_t f2tf32(float x) {
    uint32_t r;
    asm("cvt.rna.tf32.f32 %0, %1;" : "=r"(r) : "f"(x));
    return r;
}

// m16n8k8 tf32 MMA, fp32 accum
__device__ __forceinline__ void mma_tf32(float* c, const uint32_t* a,
                                         uint32_t b0, uint32_t b1) {
    asm volatile(
        "mma.sync.aligned.m16n8k8.row.col.f32.tf32.tf32.f32 "
        "{%0,%1,%2,%3}, {%4,%5,%6,%7}, {%8,%9}, {%0,%1,%2,%3};"
        : "+f"(c[0]), "+f"(c[1]), "+f"(c[2]), "+f"(c[3])
        : "r"(a[0]), "r"(a[1]), "r"(a[2]), "r"(a[3]), "r"(b0), "r"(b1));
}

// ---------------------------------------------------------------------------
// Weight prep: tf32-round + interleave.
//   out word index: n*DIM + (k/32)*32 + (k%4)*8 + (k%32)/4
// ---------------------------------------------------------------------------
__global__ __launch_bounds__(256) void prep_w_kernel(
    const float* __restrict__ W0, const float* __restrict__ W1,
    const float* __restrict__ W2, const float* __restrict__ W3,
    float* __restrict__ Wt)
{
    const int i = blockIdx.x * blockDim.x + threadIdx.x;   // over 4M elems
    const int w = i >> 20;
    const int e = i & ((1 << 20) - 1);
    const float* src = (w == 0) ? W0 : (w == 1) ? W1 : (w == 2) ? W2 : W3;
    const int n = e >> 10, k = e & 1023;
    const int kc = k >> 5, km = k & 31, c = km & 3, k4 = km >> 2;
    const uint32_t v = f2tf32(src[(size_t)n * DIM + k]);
    reinterpret_cast<uint32_t*>(Wt)[(size_t)w * DIM * DIM
        + (size_t)n * DIM + kc * 32 + c * 8 + k4] = v;
}

// ---------------------------------------------------------------------------
// TF32 GEMM-NT:  C = A @ B^T (+bias);  A fp32 [M,K] (in-loop cvt), Bt
//   prepped tf32 weights.
//   CTA 128x128, 8 warps (2x4), warp tile 64x32, K-chunk 32, 2-stage
//   pipeline, 2 CTAs/SM: two independent barrier domains (the R10/R12
//   measured win) x 8 warps each (double the intra-domain stall filling).
//   launch_bounds(256,2) caps regs at 128 (acc 64 + frags 32 + addressing).
// smem per stage (43008 B):
//   A @0:      128 rows x 144B (stride 36 words -> scalar LDS conflict-free)
//   B @18432:  128 rows x 192B (4 c-blocks x (8 data + 4 pad) words
//              -> LDS.128 fragment loads conflict-free)
// ---------------------------------------------------------------------------
#define GBM 128
#define GBN 128
#define GKC 32
#define A_STAGE 18432
#define B_STAGE 24576
#define STAGE_BYTES (A_STAGE + B_STAGE)      // 43008
#define NSTAGE 2
#define GEMM_SMEM (NSTAGE * STAGE_BYTES)     // 86016
#define GTHREADS 256

__global__ __launch_bounds__(GTHREADS, 2) void gemm_tf32_kernel(
    const float* __restrict__ A0, const float* __restrict__ A1,
    const float* __restrict__ A2,
    const float* __restrict__ B0, const float* __restrict__ B1,
    const float* __restrict__ B2,
    float* __restrict__ C0, float* __restrict__ C1, float* __restrict__ C2,
    const float* __restrict__ bias)
{
    const float* A = (blockIdx.z == 0) ? A0 : (blockIdx.z == 1) ? A1 : A2;
    const float* B = (blockIdx.z == 0) ? B0 : (blockIdx.z == 1) ? B1 : B2;
    float*       C = (blockIdx.z == 0) ? C0 : (blockIdx.z == 1) ? C1 : C2;

    extern __shared__ char smem[];
    const uint32_t sbase = smem_u32(smem);

    const int tid  = threadIdx.x;
    const int wid  = tid >> 5;
    const int lane = tid & 31;
    const int wm   = wid & 1;            // 2 warp-rows (64 rows each)
    const int wn   = wid >> 1;           // 4 warp-cols (32 cols each)
    const int row0 = blockIdx.y * GBM;
    const int col0 = blockIdx.x * GBN;

    const int g = lane >> 2;             // groupID (0..7)
    const int c = lane & 3;              // threadID_in_group

    uint32_t aBase[4];                   // A row base per mi (words)
    #pragma unroll
    for (int mi = 0; mi < 4; mi++)
        aBase[mi] = (uint32_t)((wm * 64 + mi * 16 + g) * 36 + c);
    uint32_t bBase[4];                   // B row base per ni (bytes)
    #pragma unroll
    for (int ni = 0; ni < 4; ni++)
        bBase[ni] = (uint32_t)((wn * 32 + ni * 8 + g) * 192 + c * 48);

    float acc[4][4][4];
    #pragma unroll
    for (int mi = 0; mi < 4; mi++)
        #pragma unroll
        for (int ni = 0; ni < 4; ni++)
            #pragma unroll
            for (int r = 0; r < 4; r++) acc[mi][ni][r] = 0.f;

    // chunk loader: A 1024 + B 1024 16B pieces = 8 per thread
    auto load_chunk = [&](int stage, int kc) {
        const uint32_t sb = sbase + stage * STAGE_BYTES;
        #pragma unroll
        for (int it = 0; it < 4; it++) {
            const int i = tid + it * GTHREADS;
            const int r = i >> 3, c4 = i & 7;
            cp_async16(sb + r * 144 + c4 * 16,
                       A + (size_t)(row0 + r) * DIM + kc * 32 + c4 * 4);
        }
        #pragma unroll
        for (int it = 0; it < 4; it++) {
            const int i = tid + it * GTHREADS;
            const int r = i >> 3, p = i & 7;
            cp_async16(sb + A_STAGE + r * 192 + (p >> 1) * 48 + (p & 1) * 16,
                       B + (size_t)(col0 + r) * DIM + kc * 32 + p * 4);
        }
    };

    load_chunk(0, 0);
    cp_commit();

    const int NCHUNK = DIM / GKC;   // 32
    for (int ch = 0; ch < NCHUNK; ch++) {
        cp_wait<0>();                   // chunk ch resident (this thread)
        __syncthreads();                // visibility + stage (ch+1)&1 retired
        if (ch + 1 < NCHUNK) {
            load_chunk((ch + 1) & 1, ch + 1);
            cp_commit();
        }

        const uint32_t sb   = sbase + (ch & 1) * STAGE_BYTES;
        const uint32_t aOff = (sb - sbase) / 4;          // word offset
        const uint32_t bOff = (sb - sbase) + A_STAGE;    // byte offset

        #pragma unroll
        for (int t = 0; t < 2; t++) {
            float4 bf[4];
            #pragma unroll
            for (int ni = 0; ni < 4; ni++)
                bf[ni] = *reinterpret_cast<const float4*>(
                    smem + bOff + bBase[ni] + t * 16);

            #pragma unroll
            for (int s2 = 0; s2 < 2; s2++) {
                const int s = 2 * t + s2;
                uint32_t a[4][4];
                #pragma unroll
                for (int mi = 0; mi < 4; mi++) {
                    const float* ar = reinterpret_cast<const float*>(smem)
                                    + aOff + aBase[mi] + s * 8;
                    a[mi][0] = f2tf32(ar[0]);
                    a[mi][1] = f2tf32(ar[8 * 36]);
                    a[mi][2] = f2tf32(ar[4]);
                    a[mi][3] = f2tf32(ar[8 * 36 + 4]);
                }
                #pragma unroll
                for (int mi = 0; mi < 4; mi++)
                    #pragma unroll
                    for (int ni = 0; ni < 4; ni++) {
                        const uint32_t b0 = (s2 == 0) ? __float_as_uint(bf[ni].x)
                                                      : __float_as_uint(bf[ni].z);
                        const uint32_t b1 = (s2 == 0) ? __float_as_uint(bf[ni].y)
                                                      : __float_as_uint(bf[ni].w);
                        mma_tf32(acc[mi][ni], a[mi], b0, b1);
                    }
            }
        }
    }

    // epilogue
    const int eg = lane >> 2;
    const int tg = lane & 3;
    #pragma unroll
    for (int mi = 0; mi < 4; mi++) {
        const int r0 = row0 + wm * 64 + mi * 16 + eg;
        #pragma unroll
        for (int ni = 0; ni < 4; ni++) {
            const int cc = col0 + wn * 32 + ni * 8 + tg * 2;
            float b0 = 0.f, b1 = 0.f;
            if (bias) { b0 = bias[cc]; b1 = bias[cc + 1]; }
            float2 v0 = make_float2(acc[mi][ni][0] + b0, acc[mi][ni][1] + b1);
            float2 v1 = make_float2(acc[mi][ni][2] + b0, acc[mi][ni][3] + b1);
            *reinterpret_cast<float2*>(&C[(size_t)r0 * DIM + cc]) = v0;
            *reinterpret_cast<float2*>(&C[(size_t)(r0 + 8) * DIM + cc]) = v1;
        }
    }
}

// ---------------------------------------------------------------------------
// Per-token head-mixing attention + permuted fp32 store.
// 2 tokens per 256-thread block.
// ---------------------------------------------------------------------------
__global__ __launch_bounds__(256) void attn_kernel(
    const float* __restrict__ Q, const float* __restrict__ K,
    const float* __restrict__ V, float* __restrict__ Y)
{
    const int sel = threadIdx.x >> 7;            // which token of the pair
    const int tid = threadIdx.x & 127;
    const int t   = blockIdx.x * 2 + sel;
    const int n   = t & (SEQ - 1);
    const int b   = t >> 11;

    const float* q = Q + (size_t)t * DIM;
    const float* k = K + (size_t)t * DIM;
    const float* v = V + (size_t)t * DIM;

    __shared__ float sq[2][HEADS * 65];
    __shared__ float sk[2][HEADS * 65];
    __shared__ float sv[2][DIM];
    __shared__ float sl[2][HEADS * HEADS];

    #pragma unroll
    for (int i = tid; i < 256; i += 128) {
        const int r = i >> 4;
        const int cc = (i & 15) << 2;
        float4 a = reinterpret_cast<const float4*>(q)[i];
        sq[sel][r * 65 + cc + 0] = a.x; sq[sel][r * 65 + cc + 1] = a.y;
        sq[sel][r * 65 + cc + 2] = a.z; sq[sel][r * 65 + cc + 3] = a.w;
        float4 bb = reinterpret_cast<const float4*>(k)[i];
        sk[sel][r * 65 + cc + 0] = bb.x; sk[sel][r * 65 + cc + 1] = bb.y;
        sk[sel][r * 65 + cc + 2] = bb.z; sk[sel][r * 65 + cc + 3] = bb.w;
        reinterpret_cast<float4*>(sv[sel])[i] = reinterpret_cast<const float4*>(v)[i];
    }
    __syncthreads();

    #pragma unroll
    for (int e = tid; e < 256; e += 128) {
        const int h = e >> 4;
        const int gg = e & 15;
        float s = 0.f;
        #pragma unroll
        for (int d = 0; d < HDIM; d++)
            s += sq[sel][h * 65 + d] * sk[sel][gg * 65 + d];
        sl[sel][h * 16 + gg] = s * 0.125f;
    }
    __syncthreads();

    if (tid < HEADS) {
        float mx = -1e30f;
        #pragma unroll
        for (int gg = 0; gg < 16; gg++) mx = fmaxf(mx, sl[sel][tid * 16 + gg]);
        float sum = 0.f;
        #pragma unroll
        for (int gg = 0; gg < 16; gg++) {
            const float e = __expf(sl[sel][tid * 16 + gg] - mx);
            sl[sel][tid * 16 + gg] = e;
            sum += e;
        }
        const float inv = 1.f / sum;
        #pragma unroll
        for (int gg = 0; gg < 16; gg++) sl[sel][tid * 16 + gg] *= inv;
    }
    __syncthreads();

    float* yb = Y + (size_t)b * (SEQ * DIM);
    #pragma unroll
    for (int e = tid; e < 1024; e += 128) {
        const int h = e >> 6;
        const int d = e & 63;
        float s = 0.f;
        #pragma unroll
        for (int gg = 0; gg < 16; gg++)
            s += sl[sel][h * 16 + gg] * sv[sel][gg * 64 + d];
        const int nn = h * 128 + (n >> 4);
        const int cc = ((n & 15) << 6) + d;
        yb[(size_t)nn * DIM + cc] = s;
    }
}

// ---------------------------------------------------------------------------
// kernel_launch
// ---------------------------------------------------------------------------
extern "C" void kernel_launch(void* const* d_in, const int* in_sizes, int n_in,
                              void* d_out, int out_size)
{
    const float* query = (const float*)d_in[0];
    const float* key   = (const float*)d_in[1];
    const float* value = (const float*)d_in[2];
    const float* Wq    = (const float*)d_in[5];
    const float* Wk    = (const float*)d_in[6];
    const float* Wv    = (const float*)d_in[7];
    const float* Wp    = (const float*)d_in[8];
    const float* bp    = (const float*)d_in[9];
    float* out = (float*)d_out;

    float *Qb, *Kb, *Vb, *Yb, *Wt;
    cudaGetSymbolAddress((void**)&Qb, g_Q);
    cudaGetSymbolAddress((void**)&Kb, g_K);
    cudaGetSymbolAddress((void**)&Vb, g_V);
    cudaGetSymbolAddress((void**)&Yb, g_Y);
    cudaGetSymbolAddress((void**)&Wt, g_Wt);

    cudaFuncSetAttribute(gemm_tf32_kernel,
                         cudaFuncAttributeMaxDynamicSharedMemorySize, GEMM_SMEM);

    // weight prep: tf32-round + interleave (4M elems)
    prep_w_kernel<<<4 * DIM * DIM / 256, 256>>>(Wq, Wk, Wv, Wp, Wt);

    const size_t WSZ = (size_t)DIM * DIM;
    // merged Q/K/V projections: grid.z = 3
    {
        dim3 grid(DIM / GBN, TOKENS / GBM, 3);   // (8, 128, 3) = 3072 CTAs
        gemm_tf32_kernel<<<grid, GTHREADS, GEMM_SMEM>>>(
            query, key, value,
            Wt + 0 * WSZ, Wt + 1 * WSZ, Wt + 2 * WSZ,
            Qb, Kb, Vb, nullptr);
    }

    attn_kernel<<<TOKENS / 2, 256>>>(Qb, Kb, Vb, Yb);

    // output projection (+bias)
    {
        dim3 grid(DIM / GBN, TOKENS / GBM, 1);   // (8, 128, 1) = 1024 CTAs
        gemm_tf32_kernel<<<grid, GTHREADS, GEMM_SMEM>>>(
            Yb, Yb, Yb,
            Wt + 3 * WSZ, Wt + 3 * WSZ, Wt + 3 * WSZ,
            out, out, out, bp);
    }
}

// round 15
// speedup vs baseline: 1.0450x; 1.0450x over previous
#include <cuda_runtime.h>
#include <cuda_bf16.h>
#include <cstdint>
#include <cstddef>

// ---------------------------------------------------------------------------
// Problem constants
// ---------------------------------------------------------------------------
#define BATCH   8
#define SEQ     2048
#define DIM     1024
#define HEADS   16
#define HDIM    64
#define TOKENS  (BATCH * SEQ)          // 16384
#define ELEMS   (TOKENS * DIM)         // 16,777,216

// ---------------------------------------------------------------------------
// Scratch (allocation-free rule: __device__ globals)
// ---------------------------------------------------------------------------
__device__ __align__(256) float g_Q[ELEMS];
__device__ __align__(256) float g_K[ELEMS];
__device__ __align__(256) float g_V[ELEMS];
__device__ __align__(256) float g_Y[ELEMS];             // attn out (fp32)
__device__ __align__(256) float g_Wt[4][DIM * DIM];     // weights, tf32 + interleaved

// ---------------------------------------------------------------------------
// PTX helpers (sm_80-level; tcgen05 rejected by compute_103 virtual arch)
// ---------------------------------------------------------------------------
__device__ __forceinline__ uint32_t smem_u32(const void* p) {
    uint32_t a;
    asm("{ .reg .u64 t; cvta.to.shared.u64 t, %1; cvt.u32.u64 %0, t; }"
        : "=r"(a) : "l"(p));
    return a;
}

__device__ __forceinline__ void cp_async16(uint32_t dst, const void* src) {
    asm volatile("cp.async.cg.shared.global [%0], [%1], 16;"
                 :: "r"(dst), "l"(src) : "memory");
}
__device__ __forceinline__ void cp_commit() {
    asm volatile("cp.async.commit_group;" ::: "memory");
}
template <int N>
__device__ __forceinline__ void cp_wait() {
    asm volatile("cp.async.wait_group %0;" :: "n"(N) : "memory");
}

__device__ __forceinline__ uint32_t f2tf32(float x) {
    uint32_t r;
    asm("cvt.rna.tf32.f32 %0, %1;" : "=r"(r) : "f"(x));
    return r;
}

// m16n8k8 tf32 MMA, fp32 accum
__device__ __forceinline__ void mma_tf32(float* c, const uint32_t* a,
                                         uint32_t b0, uint32_t b1) {
    asm volatile(
        "mma.sync.aligned.m16n8k8.row.col.f32.tf32.tf32.f32 "
        "{%0,%1,%2,%3}, {%4,%5,%6,%7}, {%8,%9}, {%0,%1,%2,%3};"
        : "+f"(c[0]), "+f"(c[1]), "+f"(c[2]), "+f"(c[3])
        : "r"(a[0]), "r"(a[1]), "r"(a[2]), "r"(a[3]), "r"(b0), "r"(b1));
}

// ---------------------------------------------------------------------------
// Weight prep: tf32-round + interleave.
//   out word index: n*DIM + (k/32)*32 + (k%4)*8 + (k%32)/4
// ---------------------------------------------------------------------------
__global__ __launch_bounds__(256) void prep_w_kernel(
    const float* __restrict__ W0, const float* __restrict__ W1,
    const float* __restrict__ W2, const float* __restrict__ W3,
    float* __restrict__ Wt)
{
    const int i = blockIdx.x * blockDim.x + threadIdx.x;   // over 4M elems
    const int w = i >> 20;
    const int e = i & ((1 << 20) - 1);
    const float* src = (w == 0) ? W0 : (w == 1) ? W1 : (w == 2) ? W2 : W3;
    const int n = e >> 10, k = e & 1023;
    const int kc = k >> 5, km = k & 31, c = km & 3, k4 = km >> 2;
    const uint32_t v = f2tf32(src[(size_t)n * DIM + k]);
    reinterpret_cast<uint32_t*>(Wt)[(size_t)w * DIM * DIM
        + (size_t)n * DIM + kc * 32 + c * 8 + k4] = v;
}

// ---------------------------------------------------------------------------
// TF32 GEMM-NT:  C = A @ B^T (+bias);  A fp32 [M,K] (in-loop cvt), Bt
//   prepped tf32 weights.  EXACT R12 datapath (measured best: 248us/GEMM):
//   CTA 128x128, 4 warps (2x2), warp tile 64x64, K-chunk 32, 2-stage
//   pipeline, 2 CTAs/SM (two independent barrier domains per SM).
// smem per stage (43008 B):
//   A @0:      128 rows x 144B (stride 36 words -> scalar LDS conflict-free)
//   B @18432:  128 rows x 192B (4 c-blocks x (8 data + 4 pad) words
//              -> LDS.128 fragment loads conflict-free)
// ---------------------------------------------------------------------------
#define GBM 128
#define GBN 128
#define GKC 32
#define A_STAGE 18432
#define B_STAGE 24576
#define STAGE_BYTES (A_STAGE + B_STAGE)      // 43008
#define NSTAGE 2
#define GEMM_SMEM (NSTAGE * STAGE_BYTES)     // 86016
#define GTHREADS 128

__global__ __launch_bounds__(GTHREADS, 2) void gemm_tf32_kernel(
    const float* __restrict__ A0, const float* __restrict__ A1,
    const float* __restrict__ A2,
    const float* __restrict__ B0, const float* __restrict__ B1,
    const float* __restrict__ B2,
    float* __restrict__ C0, float* __restrict__ C1, float* __restrict__ C2,
    const float* __restrict__ bias)
{
    const float* A = (blockIdx.z == 0) ? A0 : (blockIdx.z == 1) ? A1 : A2;
    const float* B = (blockIdx.z == 0) ? B0 : (blockIdx.z == 1) ? B1 : B2;
    float*       C = (blockIdx.z == 0) ? C0 : (blockIdx.z == 1) ? C1 : C2;

    extern __shared__ char smem[];
    const uint32_t sbase = smem_u32(smem);

    const int tid  = threadIdx.x;
    const int wid  = tid >> 5;
    const int lane = tid & 31;
    const int wm   = wid & 1;            // 2 warp-rows (64 rows each)
    const int wn   = wid >> 1;           // 2 warp-cols (64 cols each)
    const int row0 = blockIdx.y * GBM;
    const int col0 = blockIdx.x * GBN;

    const int g = lane >> 2;             // groupID (0..7)
    const int c = lane & 3;              // threadID_in_group

    uint32_t aBase[4];                   // A row base per mi (words)
    #pragma unroll
    for (int mi = 0; mi < 4; mi++)
        aBase[mi] = (uint32_t)((wm * 64 + mi * 16 + g) * 36 + c);
    uint32_t bBase[8];                   // B row base per ni (bytes)
    #pragma unroll
    for (int ni = 0; ni < 8; ni++)
        bBase[ni] = (uint32_t)((wn * 64 + ni * 8 + g) * 192 + c * 48);

    float acc[4][8][4];
    #pragma unroll
    for (int mi = 0; mi < 4; mi++)
        #pragma unroll
        for (int ni = 0; ni < 8; ni++)
            #pragma unroll
            for (int r = 0; r < 4; r++) acc[mi][ni][r] = 0.f;

    // chunk loader: A 1024 + B 1024 16B pieces = 16 per thread
    auto load_chunk = [&](int stage, int kc) {
        const uint32_t sb = sbase + stage * STAGE_BYTES;
        #pragma unroll
        for (int it = 0; it < 8; it++) {
            const int i = tid + it * GTHREADS;
            const int r = i >> 3, c4 = i & 7;
            cp_async16(sb + r * 144 + c4 * 16,
                       A + (size_t)(row0 + r) * DIM + kc * 32 + c4 * 4);
        }
        #pragma unroll
        for (int it = 0; it < 8; it++) {
            const int i = tid + it * GTHREADS;
            const int r = i >> 3, p = i & 7;
            cp_async16(sb + A_STAGE + r * 192 + (p >> 1) * 48 + (p & 1) * 16,
                       B + (size_t)(col0 + r) * DIM + kc * 32 + p * 4);
        }
    };

    load_chunk(0, 0);
    cp_commit();

    const int NCHUNK = DIM / GKC;   // 32
    for (int ch = 0; ch < NCHUNK; ch++) {
        cp_wait<0>();                   // chunk ch resident
        __syncthreads();                // + all warps done with chunk ch-1
        if (ch + 1 < NCHUNK) {          // safe: stage (ch+1)&1 retired
            load_chunk((ch + 1) & 1, ch + 1);
            cp_commit();
        }

        const uint32_t sb   = sbase + (ch & 1) * STAGE_BYTES;
        const uint32_t aOff = (sb - sbase) / 4;          // word offset
        const uint32_t bOff = (sb - sbase) + A_STAGE;    // byte offset

        #pragma unroll
        for (int t = 0; t < 2; t++) {
            float4 bf[8];
            #pragma unroll
            for (int ni = 0; ni < 8; ni++)
                bf[ni] = *reinterpret_cast<const float4*>(
                    smem + bOff + bBase[ni] + t * 16);

            #pragma unroll
            for (int s2 = 0; s2 < 2; s2++) {
                const int s = 2 * t + s2;
                uint32_t a[4][4];
                #pragma unroll
                for (int mi = 0; mi < 4; mi++) {
                    const float* ar = reinterpret_cast<const float*>(smem)
                                    + aOff + aBase[mi] + s * 8;
                    a[mi][0] = f2tf32(ar[0]);
                    a[mi][1] = f2tf32(ar[8 * 36]);
                    a[mi][2] = f2tf32(ar[4]);
                    a[mi][3] = f2tf32(ar[8 * 36 + 4]);
                }
                #pragma unroll
                for (int mi = 0; mi < 4; mi++)
                    #pragma unroll
                    for (int ni = 0; ni < 8; ni++) {
                        const uint32_t b0 = (s2 == 0) ? __float_as_uint(bf[ni].x)
                                                      : __float_as_uint(bf[ni].z);
                        const uint32_t b1 = (s2 == 0) ? __float_as_uint(bf[ni].y)
                                                      : __float_as_uint(bf[ni].w);
                        mma_tf32(acc[mi][ni], a[mi], b0, b1);
                    }
            }
        }
    }

    // epilogue
    const int eg = lane >> 2;
    const int tg = lane & 3;
    #pragma unroll
    for (int mi = 0; mi < 4; mi++) {
        const int r0 = row0 + wm * 64 + mi * 16 + eg;
        #pragma unroll
        for (int ni = 0; ni < 8; ni++) {
            const int cc = col0 + wn * 64 + ni * 8 + tg * 2;
            float b0 = 0.f, b1 = 0.f;
            if (bias) { b0 = bias[cc]; b1 = bias[cc + 1]; }
            float2 v0 = make_float2(acc[mi][ni][0] + b0, acc[mi][ni][1] + b1);
            float2 v1 = make_float2(acc[mi][ni][2] + b0, acc[mi][ni][3] + b1);
            *reinterpret_cast<float2*>(&C[(size_t)r0 * DIM + cc]) = v0;
            *reinterpret_cast<float2*>(&C[(size_t)(r0 + 8) * DIM + cc]) = v1;
        }
    }
}

// ---------------------------------------------------------------------------
// Per-token head-mixing attention + permuted fp32 store.
// 4 tokens per 512-thread block (amortizes per-block fixed costs further;
// 1->2 tokens/block was measured worth ~30us).
// ---------------------------------------------------------------------------
__global__ __launch_bounds__(512) void attn_kernel(
    const float* __restrict__ Q, const float* __restrict__ K,
    const float* __restrict__ V, float* __restrict__ Y)
{
    const int sel = threadIdx.x >> 7;            // which token of the quad
    const int tid = threadIdx.x & 127;
    const int t   = blockIdx.x * 4 + sel;
    const int n   = t & (SEQ - 1);
    const int b   = t >> 11;

    const float* q = Q + (size_t)t * DIM;
    const float* k = K + (size_t)t * DIM;
    const float* v = V + (size_t)t * DIM;

    __shared__ float sq[4][HEADS * 65];
    __shared__ float sk[4][HEADS * 65];
    __shared__ float sv[4][DIM];
    __shared__ float sl[4][HEADS * HEADS];

    #pragma unroll
    for (int i = tid; i < 256; i += 128) {
        const int r = i >> 4;
        const int cc = (i & 15) << 2;
        float4 a = reinterpret_cast<const float4*>(q)[i];
        sq[sel][r * 65 + cc + 0] = a.x; sq[sel][r * 65 + cc + 1] = a.y;
        sq[sel][r * 65 + cc + 2] = a.z; sq[sel][r * 65 + cc + 3] = a.w;
        float4 bb = reinterpret_cast<const float4*>(k)[i];
        sk[sel][r * 65 + cc + 0] = bb.x; sk[sel][r * 65 + cc + 1] = bb.y;
        sk[sel][r * 65 + cc + 2] = bb.z; sk[sel][r * 65 + cc + 3] = bb.w;
        reinterpret_cast<float4*>(sv[sel])[i] = reinterpret_cast<const float4*>(v)[i];
    }
    __syncthreads();

    #pragma unroll
    for (int e = tid; e < 256; e += 128) {
        const int h = e >> 4;
        const int gg = e & 15;
        float s = 0.f;
        #pragma unroll
        for (int d = 0; d < HDIM; d++)
            s += sq[sel][h * 65 + d] * sk[sel][gg * 65 + d];
        sl[sel][h * 16 + gg] = s * 0.125f;
    }
    __syncthreads();

    if (tid < HEADS) {
        float mx = -1e30f;
        #pragma unroll
        for (int gg = 0; gg < 16; gg++) mx = fmaxf(mx, sl[sel][tid * 16 + gg]);
        float sum = 0.f;
        #pragma unroll
        for (int gg = 0; gg < 16; gg++) {
            const float e = __expf(sl[sel][tid * 16 + gg] - mx);
            sl[sel][tid * 16 + gg] = e;
            sum += e;
        }
        const float inv = 1.f / sum;
        #pragma unroll
        for (int gg = 0; gg < 16; gg++) sl[sel][tid * 16 + gg] *= inv;
    }
    __syncthreads();

    float* yb = Y + (size_t)b * (SEQ * DIM);
    #pragma unroll
    for (int e = tid; e < 1024; e += 128) {
        const int h = e >> 6;
        const int d = e & 63;
        float s = 0.f;
        #pragma unroll
        for (int gg = 0; gg < 16; gg++)
            s += sl[sel][h * 16 + gg] * sv[sel][gg * 64 + d];
        const int nn = h * 128 + (n >> 4);
        const int cc = ((n & 15) << 6) + d;
        yb[(size_t)nn * DIM + cc] = s;
    }
}

// ---------------------------------------------------------------------------
// kernel_launch
// ---------------------------------------------------------------------------
extern "C" void kernel_launch(void* const* d_in, const int* in_sizes, int n_in,
                              void* d_out, int out_size)
{
    const float* query = (const float*)d_in[0];
    const float* key   = (const float*)d_in[1];
    const float* value = (const float*)d_in[2];
    const float* Wq    = (const float*)d_in[5];
    const float* Wk    = (const float*)d_in[6];
    const float* Wv    = (const float*)d_in[7];
    const float* Wp    = (const float*)d_in[8];
    const float* bp    = (const float*)d_in[9];
    float* out = (float*)d_out;

    float *Qb, *Kb, *Vb, *Yb, *Wt;
    cudaGetSymbolAddress((void**)&Qb, g_Q);
    cudaGetSymbolAddress((void**)&Kb, g_K);
    cudaGetSymbolAddress((void**)&Vb, g_V);
    cudaGetSymbolAddress((void**)&Yb, g_Y);
    cudaGetSymbolAddress((void**)&Wt, g_Wt);

    cudaFuncSetAttribute(gemm_tf32_kernel,
                         cudaFuncAttributeMaxDynamicSharedMemorySize, GEMM_SMEM);

    // weight prep: tf32-round + interleave (4M elems)
    prep_w_kernel<<<4 * DIM * DIM / 256, 256>>>(Wq, Wk, Wv, Wp, Wt);

    const size_t WSZ = (size_t)DIM * DIM;
    // merged Q/K/V projections: grid.z = 3
    {
        dim3 grid(DIM / GBN, TOKENS / GBM, 3);   // (8, 128, 3) = 3072 CTAs
        gemm_tf32_kernel<<<grid, GTHREADS, GEMM_SMEM>>>(
            query, key, value,
            Wt + 0 * WSZ, Wt + 1 * WSZ, Wt + 2 * WSZ,
            Qb, Kb, Vb, nullptr);
    }

    attn_kernel<<<TOKENS / 4, 512>>>(Qb, Kb, Vb, Yb);

    // output projection (+bias)
    {
        dim3 grid(DIM / GBN, TOKENS / GBM, 1);   // (8, 128, 1) = 1024 CTAs
        gemm_tf32_kernel<<<grid, GTHREADS, GEMM_SMEM>>>(
            Yb, Yb, Yb,
            Wt + 3 * WSZ, Wt + 3 * WSZ, Wt + 3 * WSZ,
            out, out, out, bp);
    }
}

// round 16
// speedup vs baseline: 1.3022x; 1.2462x over previous
#include <cuda_runtime.h>
#include <cuda_bf16.h>
#include <cstdint>
#include <cstddef>

// ---------------------------------------------------------------------------
// Problem constants
// ---------------------------------------------------------------------------
#define BATCH   8
#define SEQ     2048
#define DIM     1024
#define HEADS   16
#define HDIM    64
#define TOKENS  (BATCH * SEQ)          // 16384
#define ELEMS   (TOKENS * DIM)         // 16,777,216

// ---------------------------------------------------------------------------
// Scratch (allocation-free rule: __device__ globals)
// ---------------------------------------------------------------------------
__device__ __align__(256) float g_Q[ELEMS];
__device__ __align__(256) float g_K[ELEMS];
__device__ __align__(256) float g_V[ELEMS];
__device__ __align__(256) float g_Y[ELEMS];             // attn out (fp32)
__device__ __align__(256) float g_Wt[4][DIM * DIM];     // weights, tf32 + interleaved

// ---------------------------------------------------------------------------
// PTX helpers (sm_80-level; tcgen05 rejected by compute_103 virtual arch)
// ---------------------------------------------------------------------------
__device__ __forceinline__ uint32_t smem_u32(const void* p) {
    uint32_t a;
    asm("{ .reg .u64 t; cvta.to.shared.u64 t, %1; cvt.u32.u64 %0, t; }"
        : "=r"(a) : "l"(p));
    return a;
}

__device__ __forceinline__ void cp_async16(uint32_t dst, const void* src) {
    asm volatile("cp.async.cg.shared.global [%0], [%1], 16;"
                 :: "r"(dst), "l"(src) : "memory");
}
__device__ __forceinline__ void cp_commit() {
    asm volatile("cp.async.commit_group;" ::: "memory");
}
template <int N>
__device__ __forceinline__ void cp_wait() {
    asm volatile("cp.async.wait_group %0;" :: "n"(N) : "memory");
}

__device__ __forceinline__ uint32_t f2tf32(float x) {
    uint32_t r;
    asm("cvt.rna.tf32.f32 %0, %1;" : "=r"(r) : "f"(x));
    return r;
}

// m16n8k8 tf32 MMA, fp32 accum
__device__ __forceinline__ void mma_tf32(float* c, const uint32_t* a,
                                         uint32_t b0, uint32_t b1) {
    asm volatile(
        "mma.sync.aligned.m16n8k8.row.col.f32.tf32.tf32.f32 "
        "{%0,%1,%2,%3}, {%4,%5,%6,%7}, {%8,%9}, {%0,%1,%2,%3};"
        : "+f"(c[0]), "+f"(c[1]), "+f"(c[2]), "+f"(c[3])
        : "r"(a[0]), "r"(a[1]), "r"(a[2]), "r"(a[3]), "r"(b0), "r"(b1));
}

// ---------------------------------------------------------------------------
// Weight prep: tf32-round + interleave.
//   out word index: n*DIM + (k/32)*32 + (k%4)*8 + (k%32)/4
// ---------------------------------------------------------------------------
__global__ __launch_bounds__(256) void prep_w_kernel(
    const float* __restrict__ W0, const float* __restrict__ W1,
    const float* __restrict__ W2, const float* __restrict__ W3,
    float* __restrict__ Wt)
{
    const int i = blockIdx.x * blockDim.x + threadIdx.x;   // over 4M elems
    const int w = i >> 20;
    const int e = i & ((1 << 20) - 1);
    const float* src = (w == 0) ? W0 : (w == 1) ? W1 : (w == 2) ? W2 : W3;
    const int n = e >> 10, k = e & 1023;
    const int kc = k >> 5, km = k & 31, c = km & 3, k4 = km >> 2;
    const uint32_t v = f2tf32(src[(size_t)n * DIM + k]);
    reinterpret_cast<uint32_t*>(Wt)[(size_t)w * DIM * DIM
        + (size_t)n * DIM + kc * 32 + c * 8 + k4] = v;
}

// ---------------------------------------------------------------------------
// TF32 GEMM-NT:  C = A @ B^T (+bias);  A fp32 [M,K] (in-loop cvt), Bt
//   prepped tf32 weights.  R12 datapath (CTA 128x128, 4 warps 2x2, warp tile
//   64x64, K-chunk 32, 2 CTAs/SM) with a 3-STAGE pipeline enabled by an
//   XOR-swizzled (unpadded) B tile:
//     B stage: 128 rows x 128B; 16B block p of row r stored at block p^(r&7).
//     cp.async write phase: 8 lanes, same r, p=0..7 -> distinct blocks.
//     fragment read phase: lanes (g,c) read block (2c+t)^g, g in {0,1} per
//     phase -> distinct blocks. Conflict-free both ways.
//   cp_wait<1> at the barrier: chunk ch must be resident, ch+1 may stream ->
//   load window spans ~2 chunk-computes (removes load-completion jitter).
// smem per stage (34816 B): A padded @0 (18432) | B swizzled @18432 (16384)
// 3 stages = 104448 B/CTA; 2 CTAs/SM = 208.9 KB.
// ---------------------------------------------------------------------------
#define GBM 128
#define GBN 128
#define GKC 32
#define A_STAGE 18432
#define B_STAGE 16384
#define STAGE_BYTES (A_STAGE + B_STAGE)      // 34816
#define NSTAGE 3
#define GEMM_SMEM (NSTAGE * STAGE_BYTES)     // 104448
#define GTHREADS 128

__global__ __launch_bounds__(GTHREADS, 2) void gemm_tf32_kernel(
    const float* __restrict__ A0, const float* __restrict__ A1,
    const float* __restrict__ A2,
    const float* __restrict__ B0, const float* __restrict__ B1,
    const float* __restrict__ B2,
    float* __restrict__ C0, float* __restrict__ C1, float* __restrict__ C2,
    const float* __restrict__ bias)
{
    const float* A = (blockIdx.z == 0) ? A0 : (blockIdx.z == 1) ? A1 : A2;
    const float* B = (blockIdx.z == 0) ? B0 : (blockIdx.z == 1) ? B1 : B2;
    float*       C = (blockIdx.z == 0) ? C0 : (blockIdx.z == 1) ? C1 : C2;

    extern __shared__ char smem[];
    const uint32_t sbase = smem_u32(smem);

    const int tid  = threadIdx.x;
    const int wid  = tid >> 5;
    const int lane = tid & 31;
    const int wm   = wid & 1;            // 2 warp-rows (64 rows each)
    const int wn   = wid >> 1;           // 2 warp-cols (64 cols each)
    const int row0 = blockIdx.y * GBM;
    const int col0 = blockIdx.x * GBN;

    const int g = lane >> 2;             // groupID (0..7)
    const int c = lane & 3;              // threadID_in_group

    uint32_t aBase[4];                   // A row base per mi (words)
    #pragma unroll
    for (int mi = 0; mi < 4; mi++)
        aBase[mi] = (uint32_t)((wm * 64 + mi * 16 + g) * 36 + c);
    uint32_t bBase[8];                   // B row base per ni (bytes)
    #pragma unroll
    for (int ni = 0; ni < 8; ni++)
        bBase[ni] = (uint32_t)((wn * 64 + ni * 8 + g) * 128);
    // per-thread B block keys for t=0,1: 16*((2c+t)^g)   (row&7 == g)
    const uint32_t bKey0 = 16u * (uint32_t)((2 * c + 0) ^ g);
    const uint32_t bKey1 = 16u * (uint32_t)((2 * c + 1) ^ g);

    float acc[4][8][4];
    #pragma unroll
    for (int mi = 0; mi < 4; mi++)
        #pragma unroll
        for (int ni = 0; ni < 8; ni++)
            #pragma unroll
            for (int r = 0; r < 4; r++) acc[mi][ni][r] = 0.f;

    // chunk loader: A 1024 + B 1024 16B pieces = 16 per thread
    auto load_chunk = [&](int stage, int kc) {
        const uint32_t sb = sbase + stage * STAGE_BYTES;
        #pragma unroll
        for (int it = 0; it < 8; it++) {
            const int i = tid + it * GTHREADS;
            const int r = i >> 3, c4 = i & 7;
            cp_async16(sb + r * 144 + c4 * 16,
                       A + (size_t)(row0 + r) * DIM + kc * 32 + c4 * 4);
        }
        #pragma unroll
        for (int it = 0; it < 8; it++) {
            const int i = tid + it * GTHREADS;
            const int r = i >> 3, p = i & 7;
            cp_async16(sb + A_STAGE + r * 128 + 16 * (p ^ (r & 7)),
                       B + (size_t)(col0 + r) * DIM + kc * 32 + p * 4);
        }
    };

    load_chunk(0, 0);
    cp_commit();
    load_chunk(1, 1);
    cp_commit();

    const int NCHUNK = DIM / GKC;   // 32
    for (int ch = 0; ch < NCHUNK; ch++) {
        if (ch + 2 < NCHUNK) cp_wait<1>(); else cp_wait<0>();
        __syncthreads();                // all warps done with chunk ch-1
        if (ch + 2 < NCHUNK) {          // stage (ch+2)%3 == (ch-1)%3: retired
            load_chunk((ch + 2) % NSTAGE, ch + 2);
            cp_commit();
        }

        const uint32_t sb   = sbase + (ch % NSTAGE) * STAGE_BYTES;
        const uint32_t aOff = (sb - sbase) / 4;          // word offset
        const uint32_t bOff = (sb - sbase) + A_STAGE;    // byte offset

        #pragma unroll
        for (int t = 0; t < 2; t++) {
            const uint32_t bKey = (t == 0) ? bKey0 : bKey1;
            float4 bf[8];
            #pragma unroll
            for (int ni = 0; ni < 8; ni++)
                bf[ni] = *reinterpret_cast<const float4*>(
                    smem + bOff + bBase[ni] + bKey);

            #pragma unroll
            for (int s2 = 0; s2 < 2; s2++) {
                const int s = 2 * t + s2;
                uint32_t a[4][4];
                #pragma unroll
                for (int mi = 0; mi < 4; mi++) {
                    const float* ar = reinterpret_cast<const float*>(smem)
                                    + aOff + aBase[mi] + s * 8;
                    a[mi][0] = f2tf32(ar[0]);
                    a[mi][1] = f2tf32(ar[8 * 36]);
                    a[mi][2] = f2tf32(ar[4]);
                    a[mi][3] = f2tf32(ar[8 * 36 + 4]);
                }
                #pragma unroll
                for (int mi = 0; mi < 4; mi++)
                    #pragma unroll
                    for (int ni = 0; ni < 8; ni++) {
                        const uint32_t b0 = (s2 == 0) ? __float_as_uint(bf[ni].x)
                                                      : __float_as_uint(bf[ni].z);
                        const uint32_t b1 = (s2 == 0) ? __float_as_uint(bf[ni].y)
                                                      : __float_as_uint(bf[ni].w);
                        mma_tf32(acc[mi][ni], a[mi], b0, b1);
                    }
            }
        }
    }

    // epilogue
    const int eg = lane >> 2;
    const int tg = lane & 3;
    #pragma unroll
    for (int mi = 0; mi < 4; mi++) {
        const int r0 = row0 + wm * 64 + mi * 16 + eg;
        #pragma unroll
        for (int ni = 0; ni < 8; ni++) {
            const int cc = col0 + wn * 64 + ni * 8 + tg * 2;
            float b0 = 0.f, b1 = 0.f;
            if (bias) { b0 = bias[cc]; b1 = bias[cc + 1]; }
            float2 v0 = make_float2(acc[mi][ni][0] + b0, acc[mi][ni][1] + b1);
            float2 v1 = make_float2(acc[mi][ni][2] + b0, acc[mi][ni][3] + b1);
            *reinterpret_cast<float2*>(&C[(size_t)r0 * DIM + cc]) = v0;
            *reinterpret_cast<float2*>(&C[(size_t)(r0 + 8) * DIM + cc]) = v1;
        }
    }
}

// ---------------------------------------------------------------------------
// Per-token head-mixing attention + permuted fp32 store.
// 2 tokens per 256-thread block (R12 measured-best config).
// ---------------------------------------------------------------------------
__global__ __launch_bounds__(256) void attn_kernel(
    const float* __restrict__ Q, const float* __restrict__ K,
    const float* __restrict__ V, float* __restrict__ Y)
{
    const int sel = threadIdx.x >> 7;            // which token of the pair
    const int tid = threadIdx.x & 127;
    const int t   = blockIdx.x * 2 + sel;
    const int n   = t & (SEQ - 1);
    const int b   = t >> 11;

    const float* q = Q + (size_t)t * DIM;
    const float* k = K + (size_t)t * DIM;
    const float* v = V + (size_t)t * DIM;

    __shared__ float sq[2][HEADS * 65];
    __shared__ float sk[2][HEADS * 65];
    __shared__ float sv[2][DIM];
    __shared__ float sl[2][HEADS * HEADS];

    #pragma unroll
    for (int i = tid; i < 256; i += 128) {
        const int r = i >> 4;
        const int cc = (i & 15) << 2;
        float4 a = reinterpret_cast<const float4*>(q)[i];
        sq[sel][r * 65 + cc + 0] = a.x; sq[sel][r * 65 + cc + 1] = a.y;
        sq[sel][r * 65 + cc + 2] = a.z; sq[sel][r * 65 + cc + 3] = a.w;
        float4 bb = reinterpret_cast<const float4*>(k)[i];
        sk[sel][r * 65 + cc + 0] = bb.x; sk[sel][r * 65 + cc + 1] = bb.y;
        sk[sel][r * 65 + cc + 2] = bb.z; sk[sel][r * 65 + cc + 3] = bb.w;
        reinterpret_cast<float4*>(sv[sel])[i] = reinterpret_cast<const float4*>(v)[i];
    }
    __syncthreads();

    #pragma unroll
    for (int e = tid; e < 256; e += 128) {
        const int h = e >> 4;
        const int gg = e & 15;
        float s = 0.f;
        #pragma unroll
        for (int d = 0; d < HDIM; d++)
            s += sq[sel][h * 65 + d] * sk[sel][gg * 65 + d];
        sl[sel][h * 16 + gg] = s * 0.125f;
    }
    __syncthreads();

    if (tid < HEADS) {
        float mx = -1e30f;
        #pragma unroll
        for (int gg = 0; gg < 16; gg++) mx = fmaxf(mx, sl[sel][tid * 16 + gg]);
        float sum = 0.f;
        #pragma unroll
        for (int gg = 0; gg < 16; gg++) {
            const float e = __expf(sl[sel][tid * 16 + gg] - mx);
            sl[sel][tid * 16 + gg] = e;
            sum += e;
        }
        const float inv = 1.f / sum;
        #pragma unroll
        for (int gg = 0; gg < 16; gg++) sl[sel][tid * 16 + gg] *= inv;
    }
    __syncthreads();

    float* yb = Y + (size_t)b * (SEQ * DIM);
    #pragma unroll
    for (int e = tid; e < 1024; e += 128) {
        const int h = e >> 6;
        const int d = e & 63;
        float s = 0.f;
        #pragma unroll
        for (int gg = 0; gg < 16; gg++)
            s += sl[sel][h * 16 + gg] * sv[sel][gg * 64 + d];
        const int nn = h * 128 + (n >> 4);
        const int cc = ((n & 15) << 6) + d;
        yb[(size_t)nn * DIM + cc] = s;
    }
}

// ---------------------------------------------------------------------------
// kernel_launch
// ---------------------------------------------------------------------------
extern "C" void kernel_launch(void* const* d_in, const int* in_sizes, int n_in,
                              void* d_out, int out_size)
{
    const float* query = (const float*)d_in[0];
    const float* key   = (const float*)d_in[1];
    const float* value = (const float*)d_in[2];
    const float* Wq    = (const float*)d_in[5];
    const float* Wk    = (const float*)d_in[6];
    const float* Wv    = (const float*)d_in[7];
    const float* Wp    = (const float*)d_in[8];
    const float* bp    = (const float*)d_in[9];
    float* out = (float*)d_out;

    float *Qb, *Kb, *Vb, *Yb, *Wt;
    cudaGetSymbolAddress((void**)&Qb, g_Q);
    cudaGetSymbolAddress((void**)&Kb, g_K);
    cudaGetSymbolAddress((void**)&Vb, g_V);
    cudaGetSymbolAddress((void**)&Yb, g_Y);
    cudaGetSymbolAddress((void**)&Wt, g_Wt);

    cudaFuncSetAttribute(gemm_tf32_kernel,
                         cudaFuncAttributeMaxDynamicSharedMemorySize, GEMM_SMEM);

    // weight prep: tf32-round + interleave (4M elems)
    prep_w_kernel<<<4 * DIM * DIM / 256, 256>>>(Wq, Wk, Wv, Wp, Wt);

    const size_t WSZ = (size_t)DIM * DIM;
    // merged Q/K/V projections: grid.z = 3
    {
        dim3 grid(DIM / GBN, TOKENS / GBM, 3);   // (8, 128, 3) = 3072 CTAs
        gemm_tf32_kernel<<<grid, GTHREADS, GEMM_SMEM>>>(
            query, key, value,
            Wt + 0 * WSZ, Wt + 1 * WSZ, Wt + 2 * WSZ,
            Qb, Kb, Vb, nullptr);
    }

    attn_kernel<<<TOKENS / 2, 256>>>(Qb, Kb, Vb, Yb);

    // output projection (+bias)
    {
        dim3 grid(DIM / GBN, TOKENS / GBM, 1);   // (8, 128, 1) = 1024 CTAs
        gemm_tf32_kernel<<<grid, GTHREADS, GEMM_SMEM>>>(
            Yb, Yb, Yb,
            Wt + 3 * WSZ, Wt + 3 * WSZ, Wt + 3 * WSZ,
            out, out, out, bp);
    }
}

// round 17
// speedup vs baseline: 1.7937x; 1.3774x over previous
#include <cuda_runtime.h>
#include <cuda_fp16.h>
#include <cstdint>
#include <cstddef>

// ---------------------------------------------------------------------------
// Problem constants
// ---------------------------------------------------------------------------
#define BATCH   8
#define SEQ     2048
#define DIM     1024
#define HEADS   16
#define HDIM    64
#define TOKENS  (BATCH * SEQ)          // 16384
#define ELEMS   (TOKENS * DIM)         // 16,777,216

// ---------------------------------------------------------------------------
// Scratch (allocation-free rule: __device__ globals)
// ---------------------------------------------------------------------------
__device__ __align__(256) float g_Q[ELEMS];
__device__ __align__(256) float g_K[ELEMS];
__device__ __align__(256) float g_V[ELEMS];
__device__ __align__(256) float g_Y[ELEMS];                     // attn out (fp32)
__device__ __align__(256) uint32_t g_Wh[4][DIM * DIM / 2];      // weights fp16x2, interleaved

// ---------------------------------------------------------------------------
// PTX helpers (sm_80-level; tcgen05 rejected by compute_103 virtual arch)
// ---------------------------------------------------------------------------
__device__ __forceinline__ uint32_t smem_u32(const void* p) {
    uint32_t a;
    asm("{ .reg .u64 t; cvta.to.shared.u64 t, %1; cvt.u32.u64 %0, t; }"
        : "=r"(a) : "l"(p));
    return a;
}

__device__ __forceinline__ void cp_async16(uint32_t dst, const void* src) {
    asm volatile("cp.async.cg.shared.global [%0], [%1], 16;"
                 :: "r"(dst), "l"(src) : "memory");
}
__device__ __forceinline__ void cp_commit() {
    asm volatile("cp.async.commit_group;" ::: "memory");
}
template <int N>
__device__ __forceinline__ void cp_wait() {
    asm volatile("cp.async.wait_group %0;" :: "n"(N) : "memory");
}

// pack two fp32 -> fp16x2 (.lo = first arg)
__device__ __forceinline__ uint32_t pack_h2(float lo, float hi) {
    uint32_t r;
    asm("cvt.rn.f16x2.f32 %0, %1, %2;" : "=r"(r) : "f"(hi), "f"(lo));
    return r;
}

// m16n8k16 fp16 MMA, fp32 accum
__device__ __forceinline__ void mma_f16(float* c, const uint32_t* a,
                                        uint32_t b0, uint32_t b1) {
    asm volatile(
        "mma.sync.aligned.m16n8k16.row.col.f32.f16.f16.f32 "
        "{%0,%1,%2,%3}, {%4,%5,%6,%7}, {%8,%9}, {%0,%1,%2,%3};"
        : "+f"(c[0]), "+f"(c[1]), "+f"(c[2]), "+f"(c[3])
        : "r"(a[0]), "r"(a[1]), "r"(a[2]), "r"(a[3]), "r"(b0), "r"(b1));
}

// ---------------------------------------------------------------------------
// Weight prep: fp32 -> fp16x2 words, interleaved for single-LDS.128 frags.
//   word w = k/2 (512 per row); within each K32 chunk (16 words, lw=w%16):
//   pos = (lw%4)*4 + lw/4.  Thread c of a group then reads ONE float4 at
//   word 4c covering both k16 steps: {b0(t0), b1(t0), b0(t1), b1(t1)}.
// ---------------------------------------------------------------------------
__global__ __launch_bounds__(256) void prep_w_kernel(
    const float* __restrict__ W0, const float* __restrict__ W1,
    const float* __restrict__ W2, const float* __restrict__ W3,
    uint32_t* __restrict__ Wh)
{
    const int i = blockIdx.x * blockDim.x + threadIdx.x;   // over 4 * 512K words
    const int w = i >> 19;
    const int e = i & ((1 << 19) - 1);
    const float* src = (w == 0) ? W0 : (w == 1) ? W1 : (w == 2) ? W2 : W3;
    const int n = e >> 9, wd = e & 511;
    const int kc = wd >> 4, lw = wd & 15;
    const int pos = (lw & 3) * 4 + (lw >> 2);
    const int k0 = wd * 2;
    const float lo = src[(size_t)n * DIM + k0];
    const float hi = src[(size_t)n * DIM + k0 + 1];
    Wh[(size_t)w * (DIM * DIM / 2) + (size_t)n * 512 + kc * 16 + pos]
        = pack_h2(lo, hi);
}

// ---------------------------------------------------------------------------
// FP16 GEMM-NT:  C = A @ B^T (+bias);  A fp32 [M,K] (cvt+pack in-loop),
//   Bh prepped fp16 weights.
//   CTA 128x128, 4 warps (2x2), warp tile 64x64, K-chunk 32 (2 k16 steps),
//   4-STAGE pipeline (cp_wait<2>: 2 chunks streaming), 2 CTAs/SM.
// smem per stage (26624 B):
//   A @0:      128 rows x 144B fp32 (stride 36 words, conflict-free scalar/v2)
//   B @18432:  128 rows x 64B fp16 (16 words; row stride 16 == 32 banks/2rows
//              -> cp.async writes AND float4 frag reads conflict-free, no pad)
// ---------------------------------------------------------------------------
#define GBM 128
#define GBN 128
#define GKC 32
#define A_STAGE 18432
#define B_STAGE 8192
#define STAGE_BYTES (A_STAGE + B_STAGE)      // 26624
#define NSTAGE 4
#define GEMM_SMEM (NSTAGE * STAGE_BYTES)     // 106496
#define GTHREADS 128

__global__ __launch_bounds__(GTHREADS, 2) void gemm_f16_kernel(
    const float* __restrict__ A0, const float* __restrict__ A1,
    const float* __restrict__ A2,
    const uint32_t* __restrict__ B0, const uint32_t* __restrict__ B1,
    const uint32_t* __restrict__ B2,
    float* __restrict__ C0, float* __restrict__ C1, float* __restrict__ C2,
    const float* __restrict__ bias)
{
    const float*    A = (blockIdx.z == 0) ? A0 : (blockIdx.z == 1) ? A1 : A2;
    const uint32_t* B = (blockIdx.z == 0) ? B0 : (blockIdx.z == 1) ? B1 : B2;
    float*          C = (blockIdx.z == 0) ? C0 : (blockIdx.z == 1) ? C1 : C2;

    extern __shared__ char smem[];
    const uint32_t sbase = smem_u32(smem);
    const float* smemF = reinterpret_cast<const float*>(smem);

    const int tid  = threadIdx.x;
    const int wid  = tid >> 5;
    const int lane = tid & 31;
    const int wm   = wid & 1;            // 2 warp-rows (64 rows each)
    const int wn   = wid >> 1;           // 2 warp-cols (64 cols each)
    const int row0 = blockIdx.y * GBM;
    const int col0 = blockIdx.x * GBN;

    const int g = lane >> 2;             // groupID (0..7)
    const int c = lane & 3;              // threadID_in_group

    uint32_t aRow[4];                    // A row word-base per mi
    #pragma unroll
    for (int mi = 0; mi < 4; mi++)
        aRow[mi] = (uint32_t)((wm * 64 + mi * 16 + g) * 36);
    uint32_t bBase[8];                   // B row byte-base per ni (+ c*16)
    #pragma unroll
    for (int ni = 0; ni < 8; ni++)
        bBase[ni] = (uint32_t)((wn * 64 + ni * 8 + g) * 64 + c * 16);

    float acc[4][8][4];
    #pragma unroll
    for (int mi = 0; mi < 4; mi++)
        #pragma unroll
        for (int ni = 0; ni < 8; ni++)
            #pragma unroll
            for (int r = 0; r < 4; r++) acc[mi][ni][r] = 0.f;

    // chunk loader: A 1024 x 16B + B 512 x 16B = 12 per thread
    auto load_chunk = [&](int stage, int kc) {
        const uint32_t sb = sbase + stage * STAGE_BYTES;
        #pragma unroll
        for (int it = 0; it < 8; it++) {
            const int i = tid + it * GTHREADS;
            const int r = i >> 3, c4 = i & 7;
            cp_async16(sb + r * 144 + c4 * 16,
                       A + (size_t)(row0 + r) * DIM + kc * 32 + c4 * 4);
        }
        #pragma unroll
        for (int it = 0; it < 4; it++) {
            const int i = tid + it * GTHREADS;
            const int r = i >> 2, c4 = i & 3;
            cp_async16(sb + A_STAGE + r * 64 + c4 * 16,
                       B + (size_t)(col0 + r) * 512 + kc * 16 + c4 * 4);
        }
    };

    load_chunk(0, 0); cp_commit();
    load_chunk(1, 1); cp_commit();
    load_chunk(2, 2); cp_commit();

    const int NCHUNK = DIM / GKC;   // 32
    for (int ch = 0; ch < NCHUNK; ch++) {
        if (ch < NCHUNK - 2)      cp_wait<2>();
        else if (ch < NCHUNK - 1) cp_wait<1>();
        else                      cp_wait<0>();
        __syncthreads();                // all warps done with chunk ch-1
        if (ch + 3 < NCHUNK) {          // stage (ch+3)%4 == (ch-1)%4: retired
            load_chunk((ch + 3) % NSTAGE, ch + 3);
            cp_commit();
        }

        const uint32_t so   = (ch % NSTAGE) * STAGE_BYTES;
        const uint32_t aOff = so / 4;              // A word offset
        const uint32_t bOff = so + A_STAGE;        // B byte offset

        // B fragments for the whole chunk: one float4 per ni
        float4 bf[8];
        #pragma unroll
        for (int ni = 0; ni < 8; ni++)
            bf[ni] = *reinterpret_cast<const float4*>(smem + bOff + bBase[ni]);

        #pragma unroll
        for (int t = 0; t < 2; t++) {
            uint32_t a[4][4];
            #pragma unroll
            for (int mi = 0; mi < 4; mi++) {
                const float* ar = smemF + aOff + aRow[mi] + t * 16 + 2 * c;
                float2 lo0 = *reinterpret_cast<const float2*>(ar);
                float2 lo8 = *reinterpret_cast<const float2*>(ar + 8 * 36);
                float2 hi0 = *reinterpret_cast<const float2*>(ar + 8);
                float2 hi8 = *reinterpret_cast<const float2*>(ar + 8 * 36 + 8);
                a[mi][0] = pack_h2(lo0.x, lo0.y);
                a[mi][1] = pack_h2(lo8.x, lo8.y);
                a[mi][2] = pack_h2(hi0.x, hi0.y);
                a[mi][3] = pack_h2(hi8.x, hi8.y);
            }
            #pragma unroll
            for (int mi = 0; mi < 4; mi++)
                #pragma unroll
                for (int ni = 0; ni < 8; ni++) {
                    const uint32_t b0 = (t == 0) ? __float_as_uint(bf[ni].x)
                                                 : __float_as_uint(bf[ni].z);
                    const uint32_t b1 = (t == 0) ? __float_as_uint(bf[ni].y)
                                                 : __float_as_uint(bf[ni].w);
                    mma_f16(acc[mi][ni], a[mi], b0, b1);
                }
        }
    }

    // epilogue
    const int eg = lane >> 2;
    const int tg = lane & 3;
    #pragma unroll
    for (int mi = 0; mi < 4; mi++) {
        const int r0 = row0 + wm * 64 + mi * 16 + eg;
        #pragma unroll
        for (int ni = 0; ni < 8; ni++) {
            const int cc = col0 + wn * 64 + ni * 8 + tg * 2;
            float b0 = 0.f, b1 = 0.f;
            if (bias) { b0 = bias[cc]; b1 = bias[cc + 1]; }
            float2 v0 = make_float2(acc[mi][ni][0] + b0, acc[mi][ni][1] + b1);
            float2 v1 = make_float2(acc[mi][ni][2] + b0, acc[mi][ni][3] + b1);
            *reinterpret_cast<float2*>(&C[(size_t)r0 * DIM + cc]) = v0;
            *reinterpret_cast<float2*>(&C[(size_t)(r0 + 8) * DIM + cc]) = v1;
        }
    }
}

// ---------------------------------------------------------------------------
// Per-token head-mixing attention + permuted fp32 store.
// 2 tokens per 256-thread block (measured-best config).
// ---------------------------------------------------------------------------
__global__ __launch_bounds__(256) void attn_kernel(
    const float* __restrict__ Q, const float* __restrict__ K,
    const float* __restrict__ V, float* __restrict__ Y)
{
    const int sel = threadIdx.x >> 7;            // which token of the pair
    const int tid = threadIdx.x & 127;
    const int t   = blockIdx.x * 2 + sel;
    const int n   = t & (SEQ - 1);
    const int b   = t >> 11;

    const float* q = Q + (size_t)t * DIM;
    const float* k = K + (size_t)t * DIM;
    const float* v = V + (size_t)t * DIM;

    __shared__ float sq[2][HEADS * 65];
    __shared__ float sk[2][HEADS * 65];
    __shared__ float sv[2][DIM];
    __shared__ float sl[2][HEADS * HEADS];

    #pragma unroll
    for (int i = tid; i < 256; i += 128) {
        const int r = i >> 4;
        const int cc = (i & 15) << 2;
        float4 a = reinterpret_cast<const float4*>(q)[i];
        sq[sel][r * 65 + cc + 0] = a.x; sq[sel][r * 65 + cc + 1] = a.y;
        sq[sel][r * 65 + cc + 2] = a.z; sq[sel][r * 65 + cc + 3] = a.w;
        float4 bb = reinterpret_cast<const float4*>(k)[i];
        sk[sel][r * 65 + cc + 0] = bb.x; sk[sel][r * 65 + cc + 1] = bb.y;
        sk[sel][r * 65 + cc + 2] = bb.z; sk[sel][r * 65 + cc + 3] = bb.w;
        reinterpret_cast<float4*>(sv[sel])[i] = reinterpret_cast<const float4*>(v)[i];
    }
    __syncthreads();

    #pragma unroll
    for (int e = tid; e < 256; e += 128) {
        const int h = e >> 4;
        const int gg = e & 15;
        float s = 0.f;
        #pragma unroll
        for (int d = 0; d < HDIM; d++)
            s += sq[sel][h * 65 + d] * sk[sel][gg * 65 + d];
        sl[sel][h * 16 + gg] = s * 0.125f;
    }
    __syncthreads();

    if (tid < HEADS) {
        float mx = -1e30f;
        #pragma unroll
        for (int gg = 0; gg < 16; gg++) mx = fmaxf(mx, sl[sel][tid * 16 + gg]);
        float sum = 0.f;
        #pragma unroll
        for (int gg = 0; gg < 16; gg++) {
            const float e = __expf(sl[sel][tid * 16 + gg] - mx);
            sl[sel][tid * 16 + gg] = e;
            sum += e;
        }
        const float inv = 1.f / sum;
        #pragma unroll
        for (int gg = 0; gg < 16; gg++) sl[sel][tid * 16 + gg] *= inv;
    }
    __syncthreads();

    float* yb = Y + (size_t)b * (SEQ * DIM);
    #pragma unroll
    for (int e = tid; e < 1024; e += 128) {
        const int h = e >> 6;
        const int d = e & 63;
        float s = 0.f;
        #pragma unroll
        for (int gg = 0; gg < 16; gg++)
            s += sl[sel][h * 16 + gg] * sv[sel][gg * 64 + d];
        const int nn = h * 128 + (n >> 4);
        const int cc = ((n & 15) << 6) + d;
        yb[(size_t)nn * DIM + cc] = s;
    }
}

// ---------------------------------------------------------------------------
// kernel_launch
// ---------------------------------------------------------------------------
extern "C" void kernel_launch(void* const* d_in, const int* in_sizes, int n_in,
                              void* d_out, int out_size)
{
    const float* query = (const float*)d_in[0];
    const float* key   = (const float*)d_in[1];
    const float* value = (const float*)d_in[2];
    const float* Wq    = (const float*)d_in[5];
    const float* Wk    = (const float*)d_in[6];
    const float* Wv    = (const float*)d_in[7];
    const float* Wp    = (const float*)d_in[8];
    const float* bp    = (const float*)d_in[9];
    float* out = (float*)d_out;

    float *Qb, *Kb, *Vb, *Yb;
    uint32_t* Wh;
    cudaGetSymbolAddress((void**)&Qb, g_Q);
    cudaGetSymbolAddress((void**)&Kb, g_K);
    cudaGetSymbolAddress((void**)&Vb, g_V);
    cudaGetSymbolAddress((void**)&Yb, g_Y);
    cudaGetSymbolAddress((void**)&Wh, g_Wh);

    cudaFuncSetAttribute(gemm_f16_kernel,
                         cudaFuncAttributeMaxDynamicSharedMemorySize, GEMM_SMEM);

    // weight prep: fp16 + interleave (2M words)
    prep_w_kernel<<<8192, 256>>>(Wq, Wk, Wv, Wp, Wh);

    const size_t WSZ = (size_t)DIM * DIM / 2;
    // merged Q/K/V projections: grid.z = 3
    {
        dim3 grid(DIM / GBN, TOKENS / GBM, 3);   // (8, 128, 3) = 3072 CTAs
        gemm_f16_kernel<<<grid, GTHREADS, GEMM_SMEM>>>(
            query, key, value,
            Wh + 0 * WSZ, Wh + 1 * WSZ, Wh + 2 * WSZ,
            Qb, Kb, Vb, nullptr);
    }

    attn_kernel<<<TOKENS / 2, 256>>>(Qb, Kb, Vb, Yb);

    // output projection (+bias)
    {
        dim3 grid(DIM / GBN, TOKENS / GBM, 1);   // (8, 128, 1) = 1024 CTAs
        gemm_f16_kernel<<<grid, GTHREADS, GEMM_SMEM>>>(
            Yb, Yb, Yb,
            Wh + 3 * WSZ, Wh + 3 * WSZ, Wh + 3 * WSZ,
            out, out, out, bp);
    }
}